// round 12
// baseline (speedup 1.0000x reference)
#include <cuda_runtime.h>
#include <cuda_bf16.h>

// PrototypeLoss: out = mean_i ||features[i] - prototypes[labels[i]]||^2
// N=131072, D=512, C=1000.
//
// R11 analysis: gather version runs at the LTS cap (~11.2 TB/s) because the
// per-row prototype gather doubles L2 traffic. This version counting-sorts
// row indices by label (labels are only 0.5 MB), then runs one block per
// class with the prototype held in registers -> prototype L2 traffic ~0,
// leaving a pure 268 MB HBM stream of features.
//
// inputs identified by element count:
//   features f32 [N,D] = 67108864, labels int [N] = 131072 (dtype sniffed),
//   protos f32 [C,D] = 512000.   output: f32 [1,1]

#define N_ROWS 131072
#define NC 1000
#define D_VEC 128                 // D/4 float4 per row

__device__ int    g_hist[NC];
__device__ int    g_off[NC + 1];
__device__ int    g_cursor[NC];
__device__ int    g_rows[N_ROWS];
__device__ int    g_is64;
__device__ double g_bpart[NC];

// ---------------- Phase Z: zero histogram + label dtype sniff ----------------
__global__ void zero_kernel(const unsigned* __restrict__ lw) {
    for (int i = threadIdx.x; i < NC; i += blockDim.x) g_hist[i] = 0;
    if (threadIdx.x == 0) {
        // int64 labels in [0,1000) -> odd 32-bit words of first 64 entries all 0.
        // For int32 that needs 64 specific labels == 0 (p ~ 1e-192).
        unsigned o = 0;
        #pragma unroll
        for (int i = 1; i < 128; i += 2) o |= lw[i];
        g_is64 = (o == 0u) ? 1 : 0;
    }
}

__device__ __forceinline__ int load_label(const void* labels_raw, int i, int is64) {
    int l = is64 ? (int)((const long long*)labels_raw)[i]
                 : ((const int*)labels_raw)[i];
    return (l < 0) ? 0 : (l >= NC ? NC - 1 : l);
}

// ---------------- Phase H: histogram of labels ----------------
__global__ __launch_bounds__(256)
void hist_kernel(const void* __restrict__ labels_raw) {
    __shared__ int sh[NC];
    for (int i = threadIdx.x; i < NC; i += blockDim.x) sh[i] = 0;
    __syncthreads();
    const int is64 = g_is64;
    const int stride = gridDim.x * blockDim.x;
    for (int i = blockIdx.x * blockDim.x + threadIdx.x; i < N_ROWS; i += stride)
        atomicAdd(&sh[load_label(labels_raw, i, is64)], 1);
    __syncthreads();
    for (int i = threadIdx.x; i < NC; i += blockDim.x)
        if (sh[i]) atomicAdd(&g_hist[i], sh[i]);
}

// ---------------- Phase P: exclusive prefix sum over 1000 bins ----------------
__global__ __launch_bounds__(1024)
void scan_kernel() {
    __shared__ int s[1024];
    const int t = threadIdx.x;
    int v = (t < NC) ? g_hist[t] : 0;
    s[t] = v;
    __syncthreads();
    #pragma unroll
    for (int off = 1; off < 1024; off <<= 1) {
        int x = (t >= off) ? s[t - off] : 0;
        __syncthreads();
        s[t] += x;
        __syncthreads();
    }
    if (t < NC) {
        const int excl = s[t] - v;
        g_off[t]    = excl;
        g_cursor[t] = excl;
    }
    if (t == 0) g_off[NC] = N_ROWS;
}

// ---------------- Phase S: scatter row indices by class ----------------
__global__ __launch_bounds__(256)
void scatter_kernel(const void* __restrict__ labels_raw) {
    const int is64 = g_is64;
    const int stride = gridDim.x * blockDim.x;
    for (int i = blockIdx.x * blockDim.x + threadIdx.x; i < N_ROWS; i += stride) {
        const int c = load_label(labels_raw, i, is64);
        const int pos = atomicAdd(&g_cursor[c], 1);
        g_rows[pos] = i;
    }
}

// ---------------- Phase M: per-class distance accumulation ----------------
__device__ __forceinline__ float row_dist_reg(const float4* __restrict__ f,
                                              const float4 pv[4], int lane) {
    float acc = 0.0f;
    #pragma unroll
    for (int j = 0; j < 4; j++) {
        float4 a = f[lane + j * 32];
        float dx = a.x - pv[j].x;
        float dy = a.y - pv[j].y;
        float dz = a.z - pv[j].z;
        float dw = a.w - pv[j].w;
        acc = fmaf(dx, dx, acc);
        acc = fmaf(dy, dy, acc);
        acc = fmaf(dz, dz, acc);
        acc = fmaf(dw, dw, acc);
    }
    return acc;
}

__global__ __launch_bounds__(256, 4)
void main_kernel(const float4* __restrict__ feat,
                 const float4* __restrict__ protos) {
    const int c    = blockIdx.x;
    const int lane = threadIdx.x & 31;
    const int wid  = threadIdx.x >> 5;
    const int beg  = g_off[c];
    const int end  = g_off[c + 1];

    // Prototype for this class, resident in registers for the whole block's work.
    float4 pv[4];
    #pragma unroll
    for (int j = 0; j < 4; j++)
        pv[j] = __ldg(&protos[(size_t)c * D_VEC + lane + j * 32]);

    float acc = 0.0f;
    // 8 warps stride the class's row list; two rows in flight per iteration.
    for (int t = beg + wid; t < end; t += 16) {
        const int r0 = g_rows[t];
        const float4* f0 = feat + (size_t)r0 * D_VEC;
        if (t + 8 < end) {
            const int r1 = g_rows[t + 8];
            const float4* f1 = feat + (size_t)r1 * D_VEC;
            acc += row_dist_reg(f0, pv, lane);
            acc += row_dist_reg(f1, pv, lane);
        } else {
            acc += row_dist_reg(f0, pv, lane);
        }
    }

    // warp reduce
    #pragma unroll
    for (int off = 16; off; off >>= 1)
        acc += __shfl_xor_sync(0xFFFFFFFFu, acc, off);

    __shared__ float ssum[8];
    if (lane == 0) ssum[wid] = acc;
    __syncthreads();
    if (wid == 0) {
        float v = (lane < 8) ? ssum[lane] : 0.0f;
        #pragma unroll
        for (int off = 4; off; off >>= 1)
            v += __shfl_xor_sync(0xFFFFFFFFu, v, off);
        if (lane == 0) g_bpart[c] = (double)v;
    }
}

// ---------------- Phase F: final reduce ----------------
__global__ __launch_bounds__(256)
void final_kernel(float* __restrict__ out) {
    const int lane = threadIdx.x & 31;
    const int wid  = threadIdx.x >> 5;
    double d = 0.0;
    for (int i = threadIdx.x; i < NC; i += blockDim.x) d += g_bpart[i];
    #pragma unroll
    for (int off = 16; off; off >>= 1)
        d += __shfl_xor_sync(0xFFFFFFFFu, d, off);
    __shared__ double ds[8];
    if (lane == 0) ds[wid] = d;
    __syncthreads();
    if (wid == 0) {
        double t = (lane < 8) ? ds[lane] : 0.0;
        #pragma unroll
        for (int off = 4; off; off >>= 1)
            t += __shfl_xor_sync(0xFFFFFFFFu, t, off);
        if (lane == 0) out[0] = (float)(t * (1.0 / (double)N_ROWS));
    }
}

extern "C" void kernel_launch(void* const* d_in, const int* in_sizes, int n_in,
                              void* d_out, int out_size) {
    const float4* feat   = 0;
    const void*   labels = 0;
    const float4* protos = 0;
    for (int i = 0; i < n_in; i++) {
        if (in_sizes[i] == N_ROWS * 512)      feat   = (const float4*)d_in[i];
        else if (in_sizes[i] == NC * 512)     protos = (const float4*)d_in[i];
        else                                  labels = d_in[i];
    }
    float* out = (float*)d_out;

    zero_kernel<<<1, 256>>>((const unsigned*)labels);
    hist_kernel<<<148, 256>>>(labels);
    scan_kernel<<<1, 1024>>>();
    scatter_kernel<<<296, 256>>>(labels);
    main_kernel<<<NC, 256>>>(feat, protos);
    final_kernel<<<1, 256>>>(out);
}